// round 3
// baseline (speedup 1.0000x reference)
#include <cuda_runtime.h>
#include <cstdint>

#define NC 5
#define NU 6144
#define NV 6144
#define ND 64
#define NB 4096
#define CAPM 448   // merged per-node list capacity: mean 307, sigma 17.4 -> 8 sigma

#define CHUNK_BYTES 32768u
#define CHUNK_U4    2048u        // uint4 per chunk
#define CHUNK_FL    8192u        // floats per chunk
#define TOTAL_BYTES (5u * 6144u * 6144u * 4u)   // 754,974,720
#define NCHUNK      (TOTAL_BYTES / CHUNK_BYTES) // 23040
#define BUILD_GRID  296

// ---------------- scratch (static device globals; no runtime allocation) ----
__device__ __align__(16) float g_msg_a[NC * NV * ND];
__device__ __align__(16) float g_msg_b[NC * NU * ND];
__device__ __align__(16) float g_hu[NU * ND];
__device__ __align__(16) float g_hv[NV * ND];
__device__ __align__(16) float g_zu[NU * ND];
__device__ __align__(16) float g_zv[NV * ND];
__device__ __align__(16) float g_zug[NB * ND];
__device__ __align__(16) float g_zvg[NB * ND];
__device__ __align__(16) float g_tmp[NC * NB * ND];
__device__ int g_rowcnt[NU];
__device__ int g_colcnt[NV];
__device__ __align__(8) unsigned short g_rowlist[NU * CAPM];  // value = c*NV+v
__device__ __align__(8) unsigned short g_collist[NV * CAPM];  // value = c*NU+u

// ---------------- small PTX helpers -----------------------------------------
__device__ __forceinline__ uint32_t smem_u32(const void* p) {
    uint32_t a;
    asm("{ .reg .u64 t; cvta.to.shared.u64 t, %1; cvt.u32.u64 %0, t; }" : "=r"(a) : "l"(p));
    return a;
}
__device__ __forceinline__ void mbar_init(uint32_t mbar, uint32_t cnt) {
    asm volatile("mbarrier.init.shared.b64 [%0], %1;" :: "r"(mbar), "r"(cnt) : "memory");
}
__device__ __forceinline__ void mbar_expect(uint32_t mbar, uint32_t bytes) {
    asm volatile("mbarrier.arrive.expect_tx.shared.b64 _, [%0], %1;" :: "r"(mbar), "r"(bytes) : "memory");
}
__device__ __forceinline__ void mbar_wait(uint32_t mbar, uint32_t parity) {
    uint32_t done = 0;
    while (!done) {
        asm volatile(
            "{\n\t.reg .pred p;\n\t"
            "mbarrier.try_wait.parity.acquire.cta.shared::cta.b64 p, [%1], %2, 0x989680;\n\t"
            "selp.b32 %0, 1, 0, p;\n\t}"
            : "=r"(done) : "r"(mbar), "r"(parity) : "memory");
    }
}
__device__ __forceinline__ void bulk_ld(uint32_t dst, const void* src, uint32_t bytes, uint32_t mbar) {
    asm volatile(
        "cp.async.bulk.shared::cluster.global.mbarrier::complete_tx::bytes [%0], [%1], %2, [%3];"
        :: "r"(dst), "l"(src), "r"(bytes), "r"(mbar) : "memory");
}

// ---------------- zero the cursors ------------------------------------------
__global__ void k_zero(void) {
    int i = blockIdx.x * blockDim.x + threadIdx.x;
    if (i < NU) g_rowcnt[i] = 0;
    if (i < NV) g_colcnt[i] = 0;
}

// ---------------- list build: TMA bulk-copy pipeline + smem scan ------------
__device__ __forceinline__ void build_handle(unsigned j) {
    unsigned c = j / (unsigned)(NU * NV);
    unsigned r = j - c * (unsigned)(NU * NV);
    unsigned uu = r / (unsigned)NV;
    unsigned vv = r - uu * (unsigned)NV;
    int s = atomicAdd(&g_rowcnt[uu], 1);
    if (s < CAPM) g_rowlist[uu * CAPM + s] = (unsigned short)(c * NV + vv);
    int t = atomicAdd(&g_colcnt[vv], 1);
    if (t < CAPM) g_collist[vv * CAPM + t] = (unsigned short)(c * NU + uu);
}

__global__ void k_build(const char* __restrict__ adj) {
    extern __shared__ __align__(16) char dsm[];
    // layout: [0, 64KB) two 32KB chunk buffers, then two mbarriers
    uint64_t* mbp = (uint64_t*)(dsm + 2 * CHUNK_BYTES);
    uint32_t mb0 = smem_u32(mbp);
    int tid = threadIdx.x;                 // 256 threads

    if (tid == 0) { mbar_init(mb0, 1); mbar_init(mb0 + 8, 1); }
    __syncthreads();

    unsigned c = blockIdx.x;
    unsigned stride = gridDim.x;
    if (c >= NCHUNK) return;

    int ph0 = 0, ph1 = 0;
    // prologue: issue chunk c into stage 0
    if (tid == 0) {
        mbar_expect(mb0, CHUNK_BYTES);
        bulk_ld(smem_u32(dsm), adj + (size_t)c * CHUNK_BYTES, CHUNK_BYTES, mb0);
    }
    int s = 0;
    for (; c < NCHUNK; c += stride) {
        unsigned nxt = c + stride;
        if (nxt < NCHUNK && tid == 0) {
            int so = s ^ 1;
            mbar_expect(mb0 + so * 8, CHUNK_BYTES);
            bulk_ld(smem_u32(dsm + so * CHUNK_BYTES),
                    adj + (size_t)nxt * CHUNK_BYTES, CHUNK_BYTES, mb0 + so * 8);
        }
        // wait for current stage
        if (s == 0) { mbar_wait(mb0, ph0); ph0 ^= 1; }
        else        { mbar_wait(mb0 + 8, ph1); ph1 ^= 1; }

        const uint4* buf = (const uint4*)(dsm + s * CHUNK_BYTES);
        unsigned base = c * CHUNK_FL;
#pragma unroll
        for (int k = tid; k < (int)CHUNK_U4; k += 256) {
            uint4 x = buf[k];
            if (x.x | x.y | x.z | x.w) {
                unsigned j = base + (unsigned)k * 4u;
                if (x.x) build_handle(j + 0u);
                if (x.y) build_handle(j + 1u);
                if (x.z) build_handle(j + 2u);
                if (x.w) build_handle(j + 3u);
            }
        }
        __syncthreads();   // all readers done with buf[s] before it is re-filled
        s ^= 1;
    }
}

// ---------------- per-class dense transform (dual-sided) --------------------
__global__ void k_transform2(const float* __restrict__ X0, const float* __restrict__ W0,
                             float* __restrict__ out0,
                             const float* __restrict__ X1, const float* __restrict__ W1,
                             float* __restrict__ out1, int N) {
    __shared__ __align__(16) float Xs[64 * 65];
    __shared__ __align__(16) float Ws[64 * 64];
    int tid = threadIdx.x;               // 256 threads
    int c = blockIdx.y;
    int n0 = blockIdx.x * 64;
    const float* X = (blockIdx.z == 0) ? X0 : X1;
    const float* W = (blockIdx.z == 0) ? W0 : W1;
    float* out = (blockIdx.z == 0) ? out0 : out1;

    const float4* X4 = (const float4*)(X + (size_t)n0 * ND);
    const float4* W4 = (const float4*)(W + (size_t)c * ND * ND);
#pragma unroll
    for (int r = 0; r < 4; r++) {
        int f = tid + r * 256;
        float4 xv = X4[f];
        int n = f >> 4, q = f & 15;
        Xs[n * 65 + 4 * q + 0] = xv.x;
        Xs[n * 65 + 4 * q + 1] = xv.y;
        Xs[n * 65 + 4 * q + 2] = xv.z;
        Xs[n * 65 + 4 * q + 3] = xv.w;
        ((float4*)Ws)[f] = W4[f];
    }
    __syncthreads();

    int te = tid & 15, tn = tid >> 4;
    float a00=0,a01=0,a02=0,a03=0, a10=0,a11=0,a12=0,a13=0;
    float a20=0,a21=0,a22=0,a23=0, a30=0,a31=0,a32=0,a33=0;
#pragma unroll 8
    for (int d = 0; d < 64; d++) {
        float4 w = *(const float4*)&Ws[d * 64 + te * 4];
        float x0 = Xs[(tn * 4 + 0) * 65 + d];
        float x1 = Xs[(tn * 4 + 1) * 65 + d];
        float x2 = Xs[(tn * 4 + 2) * 65 + d];
        float x3 = Xs[(tn * 4 + 3) * 65 + d];
        a00 += x0 * w.x; a01 += x0 * w.y; a02 += x0 * w.z; a03 += x0 * w.w;
        a10 += x1 * w.x; a11 += x1 * w.y; a12 += x1 * w.z; a13 += x1 * w.w;
        a20 += x2 * w.x; a21 += x2 * w.y; a22 += x2 * w.z; a23 += x2 * w.w;
        a30 += x3 * w.x; a31 += x3 * w.y; a32 += x3 * w.z; a33 += x3 * w.w;
    }
    float* ob = out + ((size_t)c * N + n0 + tn * 4) * ND + te * 4;
    *(float4*)(ob + 0 * ND) = make_float4(a00, a01, a02, a03);
    *(float4*)(ob + 1 * ND) = make_float4(a10, a11, a12, a13);
    *(float4*)(ob + 2 * ND) = make_float4(a20, a21, a22, a23);
    *(float4*)(ob + 3 * ND) = make_float4(a30, a31, a32, a33);
}

// ---------------- merged sparse aggregation (both sides, one launch) --------
__device__ __forceinline__ void gather_one(float* __restrict__ out,
                                           const float* __restrict__ msg,
                                           const int* __restrict__ cnt,
                                           const unsigned short* __restrict__ lists,
                                           const float* __restrict__ bias,
                                           int u, int e, int do_relu) {
    float acc = 0.f;
#pragma unroll
    for (int c = 0; c < NC; c++) acc += bias[c * ND + e];
    int m = cnt[u];
    if (m > CAPM) m = CAPM;
    const unsigned short* lp = lists + (size_t)u * CAPM;
    int i = 0;
    for (; i + 8 <= m; i += 8) {
        ushort4 p0 = *(const ushort4*)(lp + i);
        ushort4 p1 = *(const ushort4*)(lp + i + 4);
        float v0 = msg[(unsigned)p0.x * ND + e];
        float v1 = msg[(unsigned)p0.y * ND + e];
        float v2 = msg[(unsigned)p0.z * ND + e];
        float v3 = msg[(unsigned)p0.w * ND + e];
        float v4 = msg[(unsigned)p1.x * ND + e];
        float v5 = msg[(unsigned)p1.y * ND + e];
        float v6 = msg[(unsigned)p1.z * ND + e];
        float v7 = msg[(unsigned)p1.w * ND + e];
        acc += ((v0 + v1) + (v2 + v3)) + ((v4 + v5) + (v6 + v7));
    }
    for (; i < m; i++) acc += msg[(unsigned)lp[i] * ND + e];
    if (do_relu) acc = fmaxf(acc, 0.f);
    out[(size_t)u * ND + e] = acc;
}

__global__ void k_gather2(float* __restrict__ outA, const float* __restrict__ msgA,
                          const float* __restrict__ biasA,
                          float* __restrict__ outB, const float* __restrict__ msgB,
                          const float* __restrict__ biasB, int do_relu) {
    int b = blockIdx.x;
    int e = threadIdx.x;                 // 64 threads
    if (b < NU) gather_one(outA, msgA, g_rowcnt, g_rowlist, biasA, b, e, do_relu);
    else        gather_one(outB, msgB, g_colcnt, g_collist, biasB, b - NU, e, do_relu);
}

// ---------------- gather decoder pair rows ----------------------------------
__global__ void k_pairs(const int* __restrict__ ui, const int* __restrict__ vi) {
    int b = blockIdx.x, e = threadIdx.x;
    g_zug[b * ND + e] = g_zu[(size_t)ui[b] * ND + e];
    g_zvg[b * ND + e] = g_zv[(size_t)vi[b] * ND + e];
}

// ---------------- final dot: logits[b,c] = sum_e tmp[c,b,e] * zv[b,e] -------
__global__ void k_dot(float* __restrict__ out) {
    int b = blockIdx.x, lane = threadIdx.x;   // 32 threads
    float za = g_zvg[b * ND + lane];
    float zb = g_zvg[b * ND + 32 + lane];
#pragma unroll
    for (int c = 0; c < NC; c++) {
        const float* t = &g_tmp[((size_t)c * NB + b) * ND];
        float p = t[lane] * za + t[lane + 32] * zb;
#pragma unroll
        for (int o = 16; o; o >>= 1) p += __shfl_xor_sync(0xffffffffu, p, o);
        if (lane == 0) out[b * NC + c] = p;
    }
}

// ---------------- launcher ---------------------------------------------------
extern "C" void kernel_launch(void* const* d_in, const int* in_sizes, int n_in,
                              void* d_out, int out_size) {
    const int*   ui    = (const int*)d_in[0];
    const int*   vi    = (const int*)d_in[1];
    const float* u_emb = (const float*)d_in[2];
    const float* v_emb = (const float*)d_in[3];
    const float* W1u   = (const float*)d_in[4];
    const float* b1u   = (const float*)d_in[5];
    const float* W1v   = (const float*)d_in[6];
    const float* b1v   = (const float*)d_in[7];
    const float* W2u   = (const float*)d_in[8];
    const float* b2u   = (const float*)d_in[9];
    const float* W2v   = (const float*)d_in[10];
    const float* b2v   = (const float*)d_in[11];
    const float* Q     = (const float*)d_in[12];
    const float* adj   = (const float*)d_in[13];
    float* out = (float*)d_out;

    float *msg_a, *msg_b, *hu, *hv, *zu, *zv, *zug, *tmp;
    cudaGetSymbolAddress((void**)&msg_a, g_msg_a);
    cudaGetSymbolAddress((void**)&msg_b, g_msg_b);
    cudaGetSymbolAddress((void**)&hu, g_hu);
    cudaGetSymbolAddress((void**)&hv, g_hv);
    cudaGetSymbolAddress((void**)&zu, g_zu);
    cudaGetSymbolAddress((void**)&zv, g_zv);
    cudaGetSymbolAddress((void**)&zug, g_zug);
    cudaGetSymbolAddress((void**)&tmp, g_tmp);

    static int smem_set = 0;
    // setting a func attribute is idempotent and not a stream op; do it every call
    cudaFuncSetAttribute(k_build, cudaFuncAttributeMaxDynamicSharedMemorySize,
                         (int)(2 * CHUNK_BYTES + 64));
    (void)smem_set;

    // adjacency index build: TMA bulk-copy pipeline, scan from smem
    k_zero<<<48, 256>>>();
    k_build<<<BUILD_GRID, 256, 2 * CHUNK_BYTES + 64>>>((const char*)adj);

    // layer 1 (both sides fused per launch)
    k_transform2<<<dim3(NV / 64, NC, 2), 256>>>(v_emb, W1v, msg_a, u_emb, W1u, msg_b, NV);
    k_gather2<<<NU + NV, 64>>>(hu, msg_a, b1v, hv, msg_b, b1u, 1);

    // layer 2
    k_transform2<<<dim3(NV / 64, NC, 2), 256>>>(hv, W2u, msg_a, hu, W2v, msg_b, NV);
    k_gather2<<<NU + NV, 64>>>(zu, msg_a, b2u, zv, msg_b, b2v, 0);

    // bilinear decoder
    k_pairs<<<NB, 64>>>(ui, vi);
    k_transform2<<<dim3(NB / 64, NC, 1), 256>>>(zug, Q, tmp, zug, Q, tmp, NB);
    k_dot<<<NB, 32>>>(out);
}

// round 5
// speedup vs baseline: 2.0703x; 2.0703x over previous
#include <cuda_runtime.h>
#include <cuda_fp16.h>
#include <cstdint>

#define NC 5
#define NU 6144
#define NV 6144
#define ND 64
#define NB 4096
#define CAPM 448   // merged per-node list capacity: mean 307, sigma 17.4 -> 8 sigma

// ---------------- scratch (static device globals; no runtime allocation) ----
__device__ __align__(16) __half g_msg_a[NC * NV * ND];   // fp16 messages [C,V,D]
__device__ __align__(16) __half g_msg_b[NC * NU * ND];   // fp16 messages [C,U,D]
__device__ __align__(16) float g_hu[NU * ND];
__device__ __align__(16) float g_hv[NV * ND];
__device__ __align__(16) float g_zu[NU * ND];
__device__ __align__(16) float g_zv[NV * ND];
__device__ __align__(16) float g_zug[NB * ND];
__device__ __align__(16) float g_zvg[NB * ND];
__device__ __align__(16) float g_tmp[NC * NB * ND];
__device__ int g_rowcnt[NU];
__device__ int g_colcnt[NV];
__device__ __align__(16) unsigned short g_rowlist[NU * CAPM];  // value = c*NV+v
__device__ __align__(16) unsigned short g_collist[NV * CAPM];  // value = c*NU+u

// ---------------- bit-cast helpers ------------------------------------------
__device__ __forceinline__ unsigned h2u(half2 h) {
    return *reinterpret_cast<unsigned*>(&h);
}
__device__ __forceinline__ half2 u2h(unsigned u) {
    return *reinterpret_cast<half2*>(&u);
}

// ---------------- zero the cursors ------------------------------------------
__global__ void k_zero(void) {
    int i = blockIdx.x * blockDim.x + threadIdx.x;
    if (i < NU) g_rowcnt[i] = 0;
    if (i < NV) g_colcnt[i] = 0;
}

// ---------------- build merged direct-offset lists in ONE adj scan ----------
__device__ __forceinline__ void build_handle(unsigned j) {
    unsigned c = j / (unsigned)(NU * NV);
    unsigned r = j - c * (unsigned)(NU * NV);
    unsigned uu = r / (unsigned)NV;
    unsigned vv = r - uu * (unsigned)NV;
    int s = atomicAdd(&g_rowcnt[uu], 1);
    if (s < CAPM) g_rowlist[uu * CAPM + s] = (unsigned short)(c * NV + vv);
    int t = atomicAdd(&g_colcnt[vv], 1);
    if (t < CAPM) g_collist[vv * CAPM + t] = (unsigned short)(c * NU + uu);
}

__device__ __forceinline__ void build_vec(uint4 x, unsigned i4) {
    if (x.x | x.y | x.z | x.w) {
        unsigned j = i4 * 4u;
        if (x.x) build_handle(j + 0u);
        if (x.y) build_handle(j + 1u);
        if (x.z) build_handle(j + 2u);
        if (x.w) build_handle(j + 3u);
    }
}

__global__ void k_build(const float* __restrict__ adj) {
    const uint4* a4 = (const uint4*)adj;
    const unsigned TOT4 = (unsigned)(NC * NU * NV) / 4u;
    unsigned T = gridDim.x * blockDim.x;
    unsigned tid = blockIdx.x * blockDim.x + threadIdx.x;
    unsigned base = tid;
    for (; base + 7u * T < TOT4; base += 8u * T) {
        uint4 x0 = a4[base];
        uint4 x1 = a4[base + T];
        uint4 x2 = a4[base + 2u * T];
        uint4 x3 = a4[base + 3u * T];
        uint4 x4 = a4[base + 4u * T];
        uint4 x5 = a4[base + 5u * T];
        uint4 x6 = a4[base + 6u * T];
        uint4 x7 = a4[base + 7u * T];
        build_vec(x0, base);
        build_vec(x1, base + T);
        build_vec(x2, base + 2u * T);
        build_vec(x3, base + 3u * T);
        build_vec(x4, base + 4u * T);
        build_vec(x5, base + 5u * T);
        build_vec(x6, base + 6u * T);
        build_vec(x7, base + 7u * T);
    }
    for (; base < TOT4; base += T) build_vec(a4[base], base);
}

// ---------------- per-class dense transform (dual-sided) --------------------
// out[c,n,e] = sum_d X[n,d] W[c,d,e]; half_out selects fp16 vs fp32 output.
__global__ void k_transform2(const float* __restrict__ X0, const float* __restrict__ W0,
                             void* __restrict__ out0,
                             const float* __restrict__ X1, const float* __restrict__ W1,
                             void* __restrict__ out1, int N, int half_out) {
    __shared__ __align__(16) float Xs[64 * 65];
    __shared__ __align__(16) float Ws[64 * 64];
    int tid = threadIdx.x;               // 256 threads
    int c = blockIdx.y;
    int n0 = blockIdx.x * 64;
    const float* X = (blockIdx.z == 0) ? X0 : X1;
    const float* W = (blockIdx.z == 0) ? W0 : W1;
    void* out = (blockIdx.z == 0) ? out0 : out1;

    const float4* X4 = (const float4*)(X + (size_t)n0 * ND);
    const float4* W4 = (const float4*)(W + (size_t)c * ND * ND);
#pragma unroll
    for (int r = 0; r < 4; r++) {
        int f = tid + r * 256;
        float4 xv = X4[f];
        int n = f >> 4, q = f & 15;
        Xs[n * 65 + 4 * q + 0] = xv.x;
        Xs[n * 65 + 4 * q + 1] = xv.y;
        Xs[n * 65 + 4 * q + 2] = xv.z;
        Xs[n * 65 + 4 * q + 3] = xv.w;
        ((float4*)Ws)[f] = W4[f];
    }
    __syncthreads();

    int te = tid & 15, tn = tid >> 4;
    float a00=0,a01=0,a02=0,a03=0, a10=0,a11=0,a12=0,a13=0;
    float a20=0,a21=0,a22=0,a23=0, a30=0,a31=0,a32=0,a33=0;
#pragma unroll 8
    for (int d = 0; d < 64; d++) {
        float4 w = *(const float4*)&Ws[d * 64 + te * 4];
        float x0 = Xs[(tn * 4 + 0) * 65 + d];
        float x1 = Xs[(tn * 4 + 1) * 65 + d];
        float x2 = Xs[(tn * 4 + 2) * 65 + d];
        float x3 = Xs[(tn * 4 + 3) * 65 + d];
        a00 += x0 * w.x; a01 += x0 * w.y; a02 += x0 * w.z; a03 += x0 * w.w;
        a10 += x1 * w.x; a11 += x1 * w.y; a12 += x1 * w.z; a13 += x1 * w.w;
        a20 += x2 * w.x; a21 += x2 * w.y; a22 += x2 * w.z; a23 += x2 * w.w;
        a30 += x3 * w.x; a31 += x3 * w.y; a32 += x3 * w.z; a33 += x3 * w.w;
    }
    size_t rb = (size_t)c * N + n0 + tn * 4;
    if (half_out) {
        __half* ob = (__half*)out + rb * ND + te * 4;
        *(uint2*)(ob + 0 * ND) = make_uint2(h2u(__floats2half2_rn(a00, a01)),
                                            h2u(__floats2half2_rn(a02, a03)));
        *(uint2*)(ob + 1 * ND) = make_uint2(h2u(__floats2half2_rn(a10, a11)),
                                            h2u(__floats2half2_rn(a12, a13)));
        *(uint2*)(ob + 2 * ND) = make_uint2(h2u(__floats2half2_rn(a20, a21)),
                                            h2u(__floats2half2_rn(a22, a23)));
        *(uint2*)(ob + 3 * ND) = make_uint2(h2u(__floats2half2_rn(a30, a31)),
                                            h2u(__floats2half2_rn(a32, a33)));
    } else {
        float* ob = (float*)out + rb * ND + te * 4;
        *(float4*)(ob + 0 * ND) = make_float4(a00, a01, a02, a03);
        *(float4*)(ob + 1 * ND) = make_float4(a10, a11, a12, a13);
        *(float4*)(ob + 2 * ND) = make_float4(a20, a21, a22, a23);
        *(float4*)(ob + 3 * ND) = make_float4(a30, a31, a32, a33);
    }
}

// ---------------- merged sparse aggregation over fp16 messages --------------
// One warp per node; 2 edges per warp-iteration (16 lanes x uint2 per 128B row).
__device__ __forceinline__ void hacc(float4& a, uint2 p) {
    float2 lo = __half22float2(u2h(p.x));
    float2 hi = __half22float2(u2h(p.y));
    a.x += lo.x; a.y += lo.y; a.z += hi.x; a.w += hi.y;
}

__global__ void k_gather2(float* __restrict__ outA, const __half* __restrict__ msgA,
                          const float* __restrict__ biasA,
                          float* __restrict__ outB, const __half* __restrict__ msgB,
                          const float* __restrict__ biasB, int do_relu) {
    __shared__ __align__(16) unsigned short sidx[4][CAPM];
    int warp = threadIdx.x >> 5, lane = threadIdx.x & 31;
    int node = blockIdx.x * 4 + warp;
    bool sideA = node < NU;
    int u = sideA ? node : node - NU;
    const __half* msg = sideA ? msgA : msgB;
    const float* bias = sideA ? biasA : biasB;
    float* out = sideA ? outA : outB;
    const int* cnt = sideA ? g_rowcnt : g_colcnt;
    const unsigned short* lists = sideA ? g_rowlist : g_collist;

    int m = cnt[u];
    if (m > CAPM) m = CAPM;

    // stage this node's index list into smem (16B chunks)
    const uint4* lg = (const uint4*)(lists + (size_t)u * CAPM);
    uint4* ls = (uint4*)sidx[warp];
    for (int k = lane; k * 8 < m; k += 32) ls[k] = lg[k];
    __syncwarp();

    int hw = lane >> 4;       // which of the 2 edges per iteration
    int l4 = lane & 15;       // 4-col slot within the 64-col row
    float4 acc = make_float4(0.f, 0.f, 0.f, 0.f);
    if (hw == 0) {
#pragma unroll
        for (int c = 0; c < NC; c++) {
            float4 bv = ((const float4*)(bias + c * ND))[l4];
            acc.x += bv.x; acc.y += bv.y; acc.z += bv.z; acc.w += bv.w;
        }
    }

    const uint2* mg = (const uint2*)msg;   // 8B units; row = 16 units
    const unsigned short* si = sidx[warp];
    int mm = m & ~7;
    for (int b = 0; b < mm; b += 8) {      // 8 edges per body, 4 per lane
        unsigned o0 = si[b + 0 + hw];
        unsigned o1 = si[b + 2 + hw];
        unsigned o2 = si[b + 4 + hw];
        unsigned o3 = si[b + 6 + hw];
        uint2 p0 = mg[o0 * 16u + l4];
        uint2 p1 = mg[o1 * 16u + l4];
        uint2 p2 = mg[o2 * 16u + l4];
        uint2 p3 = mg[o3 * 16u + l4];
        hacc(acc, p0); hacc(acc, p1); hacc(acc, p2); hacc(acc, p3);
    }
    for (int b = mm; b < m; b += 2) {      // tail (<8 edges)
        int e = b + hw;
        if (e < m) {
            uint2 p = mg[(unsigned)si[e] * 16u + l4];
            hacc(acc, p);
        }
    }
    // fold the two half-warp partials together
    acc.x += __shfl_xor_sync(0xffffffffu, acc.x, 16);
    acc.y += __shfl_xor_sync(0xffffffffu, acc.y, 16);
    acc.z += __shfl_xor_sync(0xffffffffu, acc.z, 16);
    acc.w += __shfl_xor_sync(0xffffffffu, acc.w, 16);
    if (hw == 0) {
        if (do_relu) {
            acc.x = fmaxf(acc.x, 0.f); acc.y = fmaxf(acc.y, 0.f);
            acc.z = fmaxf(acc.z, 0.f); acc.w = fmaxf(acc.w, 0.f);
        }
        ((float4*)(out + (size_t)u * ND))[l4] = acc;
    }
}

// ---------------- gather decoder pair rows ----------------------------------
__global__ void k_pairs(const int* __restrict__ ui, const int* __restrict__ vi) {
    int b = blockIdx.x, e = threadIdx.x;
    g_zug[b * ND + e] = g_zu[(size_t)ui[b] * ND + e];
    g_zvg[b * ND + e] = g_zv[(size_t)vi[b] * ND + e];
}

// ---------------- final dot: logits[b,c] = sum_e tmp[c,b,e] * zv[b,e] -------
__global__ void k_dot(float* __restrict__ out) {
    int b = blockIdx.x, lane = threadIdx.x;   // 32 threads
    float za = g_zvg[b * ND + lane];
    float zb = g_zvg[b * ND + 32 + lane];
#pragma unroll
    for (int c = 0; c < NC; c++) {
        const float* t = &g_tmp[((size_t)c * NB + b) * ND];
        float p = t[lane] * za + t[lane + 32] * zb;
#pragma unroll
        for (int o = 16; o; o >>= 1) p += __shfl_xor_sync(0xffffffffu, p, o);
        if (lane == 0) out[b * NC + c] = p;
    }
}

// ---------------- launcher ---------------------------------------------------
extern "C" void kernel_launch(void* const* d_in, const int* in_sizes, int n_in,
                              void* d_out, int out_size) {
    const int*   ui    = (const int*)d_in[0];
    const int*   vi    = (const int*)d_in[1];
    const float* u_emb = (const float*)d_in[2];
    const float* v_emb = (const float*)d_in[3];
    const float* W1u   = (const float*)d_in[4];
    const float* b1u   = (const float*)d_in[5];
    const float* W1v   = (const float*)d_in[6];
    const float* b1v   = (const float*)d_in[7];
    const float* W2u   = (const float*)d_in[8];
    const float* b2u   = (const float*)d_in[9];
    const float* W2v   = (const float*)d_in[10];
    const float* b2v   = (const float*)d_in[11];
    const float* Q     = (const float*)d_in[12];
    const float* adj   = (const float*)d_in[13];
    float* out = (float*)d_out;

    __half *msg_a, *msg_b;
    float *hu, *hv, *zu, *zv, *zug, *tmp;
    cudaGetSymbolAddress((void**)&msg_a, g_msg_a);
    cudaGetSymbolAddress((void**)&msg_b, g_msg_b);
    cudaGetSymbolAddress((void**)&hu, g_hu);
    cudaGetSymbolAddress((void**)&hv, g_hv);
    cudaGetSymbolAddress((void**)&zu, g_zu);
    cudaGetSymbolAddress((void**)&zv, g_zv);
    cudaGetSymbolAddress((void**)&zug, g_zug);
    cudaGetSymbolAddress((void**)&tmp, g_tmp);

    // adjacency index build (single 755 MB LDG scan)
    k_zero<<<48, 256>>>();
    k_build<<<1184, 256>>>(adj);

    // layer 1 (both sides fused per launch; fp16 messages)
    k_transform2<<<dim3(NV / 64, NC, 2), 256>>>(v_emb, W1v, msg_a, u_emb, W1u, msg_b, NV, 1);
    k_gather2<<<(NU + NV) / 4, 128>>>(hu, msg_a, b1v, hv, msg_b, b1u, 1);

    // layer 2
    k_transform2<<<dim3(NV / 64, NC, 2), 256>>>(hv, W2u, msg_a, hu, W2v, msg_b, NV, 1);
    k_gather2<<<(NU + NV) / 4, 128>>>(zu, msg_a, b2u, zv, msg_b, b2v, 0);

    // bilinear decoder (fp32 throughout)
    k_pairs<<<NB, 64>>>(ui, vi);
    k_transform2<<<dim3(NB / 64, NC, 1), 256>>>(zug, Q, tmp, zug, Q, tmp, NB, 0);
    k_dot<<<NB, 32>>>(out);
}